// round 8
// baseline (speedup 1.0000x reference)
#include <cuda_runtime.h>

namespace {

constexpr int B = 32, V = 2, J = 17, H = 128, W = 128;
constexpr int HW = H * W;                 // 16384
constexpr int NT = 256;                   // threads per block
constexpr int PER4 = HW / (4 * NT);       // 16 float4 per thread per view
constexpr int IMG2_SZ = B * V * 2 * J;    // 2176 floats (first output)
constexpr float SC = 28.85390081777927f;  // (1/0.05) * log2(e)

__device__ __forceinline__ void inv3x3(const float* m, float inv[3][3]) {
    float a = m[0], b = m[1], c = m[2];
    float d = m[3], e = m[4], f = m[5];
    float g = m[6], h = m[7], i = m[8];
    float A = (e * i - f * h);
    float Bm = -(d * i - f * g);
    float C = (d * h - e * g);
    float det = a * A + b * Bm + c * C;
    float id = 1.0f / det;
    inv[0][0] = A * id;               inv[0][1] = -(b * i - c * h) * id; inv[0][2] = (b * f - c * e) * id;
    inv[1][0] = Bm * id;              inv[1][1] = (a * i - c * g) * id;  inv[1][2] = -(a * f - c * d) * id;
    inv[2][0] = C * id;               inv[2][1] = -(a * h - b * g) * id; inv[2][2] = (a * e - b * d) * id;
}

__device__ __forceinline__ float epi_dist(const float F[3][3], const float xi[3], const float xj[3]) {
    float l0 = F[0][0] * xj[0] + F[0][1] * xj[1] + F[0][2] * xj[2];
    float l1 = F[1][0] * xj[0] + F[1][1] * xj[1] + F[1][2] * xj[2];
    float l2 = F[2][0] * xj[0] + F[2][1] * xj[1] + F[2][2] * xj[2];
    float s = xi[0] * l0 + xi[1] * l1 + xi[2] * l2;
    float lp0 = F[0][0] * xi[0] + F[1][0] * xi[1] + F[2][0] * xi[2];
    float lp1 = F[0][1] * xi[0] + F[1][1] * xi[1] + F[2][1] * xi[2];
    float div = l0 * l0 + l1 * l1 + lp0 * lp0 + lp1 * lp1;
    return sqrtf(s * s / (div + 1e-12f));
}

__global__ __launch_bounds__(NT, 6) void adafuse_kernel(
    const float* __restrict__ hms,
    const float* __restrict__ APK, const float* __restrict__ APT,
    const float* __restrict__ LATK, const float* __restrict__ LATT,
    float* __restrict__ out)
{
    __shared__ float sw[8][9];    // per-warp partials (8 warps x up to 9 quantities)
    __shared__ float sres[12];    // reduced results + broadcast weights
    __shared__ float sgeom[50];   // APT(16) | LATT(16) | APK(9) | LATK(9)

    const int j = blockIdx.x;
    const int b = blockIdx.y;
    const int tid = threadIdx.x;
    const int wid = tid >> 5;
    const int lane = tid & 31;

    if (tid < 16)       sgeom[tid] = APT[b * 16 + tid];
    else if (tid < 32)  sgeom[tid] = LATT[b * 16 + (tid - 16)];
    else if (tid < 41)  sgeom[tid] = APK[b * 9 + (tid - 32)];
    else if (tid < 50)  sgeom[tid] = LATK[b * 9 + (tid - 41)];

    const float4* hm0 = reinterpret_cast<const float4*>(hms + (size_t)((b * 2 + 0) * J + j) * HW);
    const float4* hm1 = reinterpret_cast<const float4*>(hms + (size_t)((b * 2 + 1) * J + j) * HW);

    // element index (tid,k,comp) = 4*tid + 1024*k + comp
    // col = (4*tid) & 127 (+comp), row = ((4*tid) >> 7) + 8*k
    const float col0 = (float)((4 * tid) & 127);
    const int row0 = (4 * tid) >> 7;

    // ---- Pass 1: read both views (DRAM, default caching so lines persist in
    //      L2 for pass 2 — whole grid is one wave, input 71 MB < 126 MB L2).
    //      Max + softmax moments. (No max-subtraction: inputs in [0,1) ->
    //      exp2f(x*SC) <= 2^28.9, safe in fp32; softmax scale-invariant.) ----
    float m0 = -1e30f, m1 = -1e30f;
    float s0 = 0.f, sx0 = 0.f, sy0 = 0.f;
    float s1 = 0.f, sx1 = 0.f, sy1 = 0.f;
#pragma unroll
    for (int k = 0; k < PER4; ++k) {
        float4 A = hm0[tid + k * NT];
        float4 C = hm1[tid + k * NT];
        float rw = (float)(row0 + 8 * k);
        m0 = fmaxf(m0, fmaxf(fmaxf(A.x, A.y), fmaxf(A.z, A.w)));
        m1 = fmaxf(m1, fmaxf(fmaxf(C.x, C.y), fmaxf(C.z, C.w)));
        float e0 = exp2f(A.x * SC);
        float e1 = exp2f(A.y * SC);
        float e2 = exp2f(A.z * SC);
        float e3 = exp2f(A.w * SC);
        float es = (e0 + e1) + (e2 + e3);
        s0 += es;
        sx0 += col0 * es + (e1 + 2.f * e2 + 3.f * e3);
        sy0 += rw * es;
        float f0 = exp2f(C.x * SC);
        float f1 = exp2f(C.y * SC);
        float f2 = exp2f(C.z * SC);
        float f3 = exp2f(C.w * SC);
        float fs = (f0 + f1) + (f2 + f3);
        s1 += fs;
        sx1 += col0 * fs + (f1 + 2.f * f2 + 3.f * f3);
        sy1 += rw * fs;
    }

    // ---- Batched 8-quantity block reduction over 8 warps (2 barriers) ----
    {
        float v[8] = {m0, m1, s0, sx0, sy0, s1, sx1, sy1};
#pragma unroll
        for (int q = 0; q < 8; ++q) {
#pragma unroll
            for (int o = 16; o; o >>= 1) {
                float t = __shfl_xor_sync(0xffffffffu, v[q], o);
                v[q] = (q < 2) ? fmaxf(v[q], t) : (v[q] + t);
            }
        }
        if (lane == 0) {
#pragma unroll
            for (int q = 0; q < 8; ++q) sw[wid][q] = v[q];
        }
        __syncthreads();
        if (tid < 64) {  // 2 FULL warps: quantity g = tid>>3, partial e = tid&7
            int g = tid >> 3, e = tid & 7;
            float x = sw[e][g];
#pragma unroll
            for (int o = 4; o; o >>= 1) {
                float t = __shfl_xor_sync(0xffffffffu, x, o);
                x = (g < 2) ? fmaxf(x, t) : (x + t);
            }
            if (e == 0) sres[g] = x;
        }
        __syncthreads();
    }

    // ---- Geometry + view weights (thread 0) ----
    if (tid == 0) {
        const float* T0p = sgeom;
        const float* T1p = sgeom + 16;
        const float* K0 = sgeom + 32;
        const float* K1 = sgeom + 41;
        float R0[3][3], R1[3][3], t0v[3], t1v[3];
#pragma unroll
        for (int m = 0; m < 3; ++m) {
#pragma unroll
            for (int n = 0; n < 3; ++n) {
                R0[m][n] = T0p[m * 4 + n];
                R1[m][n] = T1p[m * 4 + n];
            }
            t0v[m] = T0p[m * 4 + 3];
            t1v[m] = T1p[m * 4 + 3];
        }
        float iK0[3][3], iK1[3][3];
        inv3x3(K0, iK0);
        inv3x3(K1, iK1);

        float r01[3][3];
#pragma unroll
        for (int m = 0; m < 3; ++m)
#pragma unroll
            for (int n = 0; n < 3; ++n)
                r01[m][n] = R0[m][0] * R1[n][0] + R0[m][1] * R1[n][1] + R0[m][2] * R1[n][2];

        float t01[3], t10[3];
#pragma unroll
        for (int m = 0; m < 3; ++m) {
            t01[m] = t0v[m] - (r01[m][0] * t1v[0] + r01[m][1] * t1v[1] + r01[m][2] * t1v[2]);
            t10[m] = t1v[m] - (r01[0][m] * t0v[0] + r01[1][m] * t0v[1] + r01[2][m] * t0v[2]);
        }

        float M01[3][3], M10[3][3];
#pragma unroll
        for (int n = 0; n < 3; ++n) {
            M01[0][n] = -t01[2] * r01[1][n] + t01[1] * r01[2][n];
            M01[1][n] =  t01[2] * r01[0][n] - t01[0] * r01[2][n];
            M01[2][n] = -t01[1] * r01[0][n] + t01[0] * r01[1][n];
            M10[0][n] = -t10[2] * r01[n][1] + t10[1] * r01[n][2];
            M10[1][n] =  t10[2] * r01[n][0] - t10[0] * r01[n][2];
            M10[2][n] = -t10[1] * r01[n][0] + t10[0] * r01[n][1];
        }

        float tmp[3][3], F01[3][3], F10[3][3];
#pragma unroll
        for (int p = 0; p < 3; ++p)
#pragma unroll
            for (int l = 0; l < 3; ++l)
                tmp[p][l] = M01[p][0] * iK1[0][l] + M01[p][1] * iK1[1][l] + M01[p][2] * iK1[2][l];
#pragma unroll
        for (int m = 0; m < 3; ++m)
#pragma unroll
            for (int l = 0; l < 3; ++l)
                F01[m][l] = iK0[0][m] * tmp[0][l] + iK0[1][m] * tmp[1][l] + iK0[2][m] * tmp[2][l];
#pragma unroll
        for (int p = 0; p < 3; ++p)
#pragma unroll
            for (int l = 0; l < 3; ++l)
                tmp[p][l] = M10[p][0] * iK0[0][l] + M10[p][1] * iK0[1][l] + M10[p][2] * iK0[2][l];
#pragma unroll
        for (int m = 0; m < 3; ++m)
#pragma unroll
            for (int l = 0; l < 3; ++l)
                F10[m][l] = iK1[0][m] * tmp[0][l] + iK1[1][m] * tmp[1][l] + iK1[2][m] * tmp[2][l];

        float rm0 = sres[0], rm1 = sres[1];
        float img0[3] = {4.f * sres[3] / sres[2], 4.f * sres[4] / sres[2], 1.f};
        float img1[3] = {4.f * sres[6] / sres[5], 4.f * sres[7] / sres[5], 1.f};
        float d01 = epi_dist(F01, img0, img1);
        float d10 = epi_dist(F10, img1, img0);

        float sc0 = rm0 - d01;
        float sc1 = rm1 - d10;
        float mm = fmaxf(sc0, sc1);
        float e0 = __expf(sc0 - mm), e1 = __expf(sc1 - mm);
        float inv = 1.f / (e0 + e1);
        float mv0 = (rm0 > 0.01f) ? rm0 : 1e6f;
        float mv1 = (rm1 > 0.01f) ? rm1 : 1e6f;
        sres[8] = e0 * inv / mv0;
        sres[9] = e1 * inv / mv1;
    }
    __syncthreads();
    const float w0 = sres[8];
    const float w1 = sres[9];

    // ---- Pass 2: re-read both views (L2 hits — single wave keeps lines
    //      resident), fuse, streaming-store both output slices, accumulate
    //      fused softmax moments ----
    float4* o0 = reinterpret_cast<float4*>(out + IMG2_SZ + (size_t)((b * 2 + 0) * J + j) * HW);
    float4* o1 = reinterpret_cast<float4*>(out + IMG2_SZ + (size_t)((b * 2 + 1) * J + j) * HW);
    float s2 = 0.f, sx2 = 0.f, sy2 = 0.f;
#pragma unroll
    for (int k = 0; k < PER4; ++k) {
        float4 A = hm0[tid + k * NT];
        float4 C = hm1[tid + k * NT];
        float rw = (float)(row0 + 8 * k);
        float4 f;
        f.x = w0 * A.x + w1 * C.x;
        f.y = w0 * A.y + w1 * C.y;
        f.z = w0 * A.z + w1 * C.z;
        f.w = w0 * A.w + w1 * C.w;
        __stcs(&o0[tid + k * NT], f);
        __stcs(&o1[tid + k * NT], f);
        float e0 = exp2f(f.x * SC);
        float e1 = exp2f(f.y * SC);
        float e2 = exp2f(f.z * SC);
        float e3 = exp2f(f.w * SC);
        float es = (e0 + e1) + (e2 + e3);
        s2 += es;
        sx2 += col0 * es + (e1 + 2.f * e2 + 3.f * e3);
        sy2 += rw * es;
    }

    // ---- Batched 3-quantity reduction (2 barriers; 1 FULL warp stage 2) ----
    {
        float v[3] = {s2, sx2, sy2};
#pragma unroll
        for (int q = 0; q < 3; ++q) {
#pragma unroll
            for (int o = 16; o; o >>= 1)
                v[q] += __shfl_xor_sync(0xffffffffu, v[q], o);
        }
        if (lane == 0) {
#pragma unroll
            for (int q = 0; q < 3; ++q) sw[wid][q] = v[q];
        }
        __syncthreads();
        if (tid < 32) {  // 1 FULL warp: g = tid>>3 (0..3; group 3 zero-padded)
            int g = tid >> 3, e = tid & 7;
            float x = (g < 3) ? sw[e][g] : 0.f;
#pragma unroll
            for (int o = 4; o; o >>= 1)
                x += __shfl_xor_sync(0xffffffffu, x, o);
            if (e == 0 && g < 3) sres[g] = x;
        }
        __syncthreads();
    }

    if (tid == 0) {
        float x2 = 4.f * sres[1] / sres[0];
        float y2 = 4.f * sres[2] / sres[0];
        int base = b * (V * 2 * J);  // img2 layout (B, V, 2, J)
        out[base + 0 * J + j] = x2;
        out[base + 1 * J + j] = y2;
        out[base + 2 * J + j] = x2;
        out[base + 3 * J + j] = y2;
    }
}

}  // namespace

extern "C" void kernel_launch(void* const* d_in, const int* in_sizes, int n_in,
                              void* d_out, int out_size) {
    const float* hms  = (const float*)d_in[0];
    const float* APK  = (const float*)d_in[1];
    const float* APT  = (const float*)d_in[2];
    const float* LATK = (const float*)d_in[3];
    const float* LATT = (const float*)d_in[4];
    float* out = (float*)d_out;
    dim3 grid(J, B);
    adafuse_kernel<<<grid, NT>>>(hms, APK, APT, LATK, LATT, out);
}

// round 9
// speedup vs baseline: 2.2201x; 2.2201x over previous
#include <cuda_runtime.h>

namespace {

constexpr int B = 32, V = 2, J = 17, H = 128, W = 128;
constexpr int HW = H * W;                 // 16384
constexpr int NT = 256;                   // threads per block
constexpr int PER4 = HW / (4 * NT);       // 16 float4 per thread per view
constexpr int IMG2_SZ = B * V * 2 * J;    // 2176 floats (first output)
constexpr float SC = 28.85390081777927f;  // (1/0.05) * log2(e)

__device__ float g_w[B * J * 2];          // per-(b,j) fused coefficients

__device__ __forceinline__ void inv3x3(const float* m, float inv[3][3]) {
    float a = m[0], b = m[1], c = m[2];
    float d = m[3], e = m[4], f = m[5];
    float g = m[6], h = m[7], i = m[8];
    float A = (e * i - f * h);
    float Bm = -(d * i - f * g);
    float C = (d * h - e * g);
    float det = a * A + b * Bm + c * C;
    float id = 1.0f / det;
    inv[0][0] = A * id;               inv[0][1] = -(b * i - c * h) * id; inv[0][2] = (b * f - c * e) * id;
    inv[1][0] = Bm * id;              inv[1][1] = (a * i - c * g) * id;  inv[1][2] = -(a * f - c * d) * id;
    inv[2][0] = C * id;               inv[2][1] = -(a * h - b * g) * id; inv[2][2] = (a * e - b * d) * id;
}

__device__ __forceinline__ float epi_dist(const float F[3][3], const float xi[3], const float xj[3]) {
    float l0 = F[0][0] * xj[0] + F[0][1] * xj[1] + F[0][2] * xj[2];
    float l1 = F[1][0] * xj[0] + F[1][1] * xj[1] + F[1][2] * xj[2];
    float l2 = F[2][0] * xj[0] + F[2][1] * xj[1] + F[2][2] * xj[2];
    float s = xi[0] * l0 + xi[1] * l1 + xi[2] * l2;
    float lp0 = F[0][0] * xi[0] + F[1][0] * xi[1] + F[2][0] * xi[2];
    float lp1 = F[0][1] * xi[0] + F[1][1] * xi[1] + F[2][1] * xi[2];
    float div = l0 * l0 + l1 * l1 + lp0 * lp0 + lp1 * lp1;
    return sqrtf(s * s / (div + 1e-12f));
}

// ============================================================================
// Kernel 1: per-(b,j) view moments + geometry -> fused coefficients w0, w1.
// Pure streaming read of both heatmap views (leaves them resident in L2).
// ============================================================================
__global__ __launch_bounds__(NT) void adafuse_weights_kernel(
    const float* __restrict__ hms,
    const float* __restrict__ APK, const float* __restrict__ APT,
    const float* __restrict__ LATK, const float* __restrict__ LATT)
{
    __shared__ float sw[8][9];
    __shared__ float sres[10];
    __shared__ float sgeom[50];

    const int j = blockIdx.x;
    const int b = blockIdx.y;
    const int tid = threadIdx.x;
    const int wid = tid >> 5;
    const int lane = tid & 31;

    if (tid < 16)       sgeom[tid] = APT[b * 16 + tid];
    else if (tid < 32)  sgeom[tid] = LATT[b * 16 + (tid - 16)];
    else if (tid < 41)  sgeom[tid] = APK[b * 9 + (tid - 32)];
    else if (tid < 50)  sgeom[tid] = LATK[b * 9 + (tid - 41)];

    const float4* hm0 = reinterpret_cast<const float4*>(hms + (size_t)((b * 2 + 0) * J + j) * HW);
    const float4* hm1 = reinterpret_cast<const float4*>(hms + (size_t)((b * 2 + 1) * J + j) * HW);

    // element index (tid,k,comp) = 4*tid + 1024*k + comp
    const float col0 = (float)((4 * tid) & 127);
    const int row0 = (4 * tid) >> 7;

    // No max-subtraction: inputs in [0,1) -> exp2f(x*SC) <= 2^28.9, fp32-safe;
    // softmax is scale-invariant.
    float m0 = -1e30f, m1 = -1e30f;
    float s0 = 0.f, sx0 = 0.f, sy0 = 0.f;
    float s1 = 0.f, sx1 = 0.f, sy1 = 0.f;
#pragma unroll
    for (int k = 0; k < PER4; ++k) {
        float4 A = hm0[tid + k * NT];
        float4 C = hm1[tid + k * NT];
        float rw = (float)(row0 + 8 * k);
        m0 = fmaxf(m0, fmaxf(fmaxf(A.x, A.y), fmaxf(A.z, A.w)));
        m1 = fmaxf(m1, fmaxf(fmaxf(C.x, C.y), fmaxf(C.z, C.w)));
        float e0 = exp2f(A.x * SC);
        float e1 = exp2f(A.y * SC);
        float e2 = exp2f(A.z * SC);
        float e3 = exp2f(A.w * SC);
        float es = (e0 + e1) + (e2 + e3);
        s0 += es;
        sx0 += col0 * es + (e1 + 2.f * e2 + 3.f * e3);
        sy0 += rw * es;
        float f0 = exp2f(C.x * SC);
        float f1 = exp2f(C.y * SC);
        float f2 = exp2f(C.z * SC);
        float f3 = exp2f(C.w * SC);
        float fs = (f0 + f1) + (f2 + f3);
        s1 += fs;
        sx1 += col0 * fs + (f1 + 2.f * f2 + 3.f * f3);
        sy1 += rw * fs;
    }

    // Batched 8-quantity block reduction over 8 warps (2 barriers)
    {
        float v[8] = {m0, m1, s0, sx0, sy0, s1, sx1, sy1};
#pragma unroll
        for (int q = 0; q < 8; ++q) {
#pragma unroll
            for (int o = 16; o; o >>= 1) {
                float t = __shfl_xor_sync(0xffffffffu, v[q], o);
                v[q] = (q < 2) ? fmaxf(v[q], t) : (v[q] + t);
            }
        }
        if (lane == 0) {
#pragma unroll
            for (int q = 0; q < 8; ++q) sw[wid][q] = v[q];
        }
        __syncthreads();
        if (tid < 64) {  // 2 FULL warps: quantity g = tid>>3, partial e = tid&7
            int g = tid >> 3, e = tid & 7;
            float x = sw[e][g];
#pragma unroll
            for (int o = 4; o; o >>= 1) {
                float t = __shfl_xor_sync(0xffffffffu, x, o);
                x = (g < 2) ? fmaxf(x, t) : (x + t);
            }
            if (e == 0) sres[g] = x;
        }
        __syncthreads();
    }

    if (tid == 0) {
        const float* T0p = sgeom;
        const float* T1p = sgeom + 16;
        const float* K0 = sgeom + 32;
        const float* K1 = sgeom + 41;
        float R0[3][3], R1[3][3], t0v[3], t1v[3];
#pragma unroll
        for (int m = 0; m < 3; ++m) {
#pragma unroll
            for (int n = 0; n < 3; ++n) {
                R0[m][n] = T0p[m * 4 + n];
                R1[m][n] = T1p[m * 4 + n];
            }
            t0v[m] = T0p[m * 4 + 3];
            t1v[m] = T1p[m * 4 + 3];
        }
        float iK0[3][3], iK1[3][3];
        inv3x3(K0, iK0);
        inv3x3(K1, iK1);

        float r01[3][3];
#pragma unroll
        for (int m = 0; m < 3; ++m)
#pragma unroll
            for (int n = 0; n < 3; ++n)
                r01[m][n] = R0[m][0] * R1[n][0] + R0[m][1] * R1[n][1] + R0[m][2] * R1[n][2];

        float t01[3], t10[3];
#pragma unroll
        for (int m = 0; m < 3; ++m) {
            t01[m] = t0v[m] - (r01[m][0] * t1v[0] + r01[m][1] * t1v[1] + r01[m][2] * t1v[2]);
            t10[m] = t1v[m] - (r01[0][m] * t0v[0] + r01[1][m] * t0v[1] + r01[2][m] * t0v[2]);
        }

        float M01[3][3], M10[3][3];
#pragma unroll
        for (int n = 0; n < 3; ++n) {
            M01[0][n] = -t01[2] * r01[1][n] + t01[1] * r01[2][n];
            M01[1][n] =  t01[2] * r01[0][n] - t01[0] * r01[2][n];
            M01[2][n] = -t01[1] * r01[0][n] + t01[0] * r01[1][n];
            M10[0][n] = -t10[2] * r01[n][1] + t10[1] * r01[n][2];
            M10[1][n] =  t10[2] * r01[n][0] - t10[0] * r01[n][2];
            M10[2][n] = -t10[1] * r01[n][0] + t10[0] * r01[n][1];
        }

        float tmp[3][3], F01[3][3], F10[3][3];
#pragma unroll
        for (int p = 0; p < 3; ++p)
#pragma unroll
            for (int l = 0; l < 3; ++l)
                tmp[p][l] = M01[p][0] * iK1[0][l] + M01[p][1] * iK1[1][l] + M01[p][2] * iK1[2][l];
#pragma unroll
        for (int m = 0; m < 3; ++m)
#pragma unroll
            for (int l = 0; l < 3; ++l)
                F01[m][l] = iK0[0][m] * tmp[0][l] + iK0[1][m] * tmp[1][l] + iK0[2][m] * tmp[2][l];
#pragma unroll
        for (int p = 0; p < 3; ++p)
#pragma unroll
            for (int l = 0; l < 3; ++l)
                tmp[p][l] = M10[p][0] * iK0[0][l] + M10[p][1] * iK0[1][l] + M10[p][2] * iK0[2][l];
#pragma unroll
        for (int m = 0; m < 3; ++m)
#pragma unroll
            for (int l = 0; l < 3; ++l)
                F10[m][l] = iK1[0][m] * tmp[0][l] + iK1[1][m] * tmp[1][l] + iK1[2][m] * tmp[2][l];

        float rm0 = sres[0], rm1 = sres[1];
        float img0[3] = {4.f * sres[3] / sres[2], 4.f * sres[4] / sres[2], 1.f};
        float img1[3] = {4.f * sres[6] / sres[5], 4.f * sres[7] / sres[5], 1.f};
        float d01 = epi_dist(F01, img0, img1);
        float d10 = epi_dist(F10, img1, img0);

        float sc0 = rm0 - d01;
        float sc1 = rm1 - d10;
        float mm = fmaxf(sc0, sc1);
        float e0 = __expf(sc0 - mm), e1 = __expf(sc1 - mm);
        float inv = 1.f / (e0 + e1);
        float mv0 = (rm0 > 0.01f) ? rm0 : 1e6f;
        float mv1 = (rm1 > 0.01f) ? rm1 : 1e6f;
        g_w[(b * J + j) * 2 + 0] = e0 * inv / mv0;
        g_w[(b * J + j) * 2 + 1] = e1 * inv / mv1;
    }
}

// ============================================================================
// Kernel 2: fuse (reads hit L2 left warm by k1), streaming-store both output
// slices, fused soft-argmax -> img2.
// ============================================================================
__global__ __launch_bounds__(NT) void adafuse_fuse_kernel(
    const float* __restrict__ hms,
    float* __restrict__ out)
{
    __shared__ float sw[8][3];
    __shared__ float sres[3];

    const int j = blockIdx.x;
    const int b = blockIdx.y;
    const int tid = threadIdx.x;
    const int wid = tid >> 5;
    const int lane = tid & 31;

    const float w0 = g_w[(b * J + j) * 2 + 0];
    const float w1 = g_w[(b * J + j) * 2 + 1];

    const float4* hm0 = reinterpret_cast<const float4*>(hms + (size_t)((b * 2 + 0) * J + j) * HW);
    const float4* hm1 = reinterpret_cast<const float4*>(hms + (size_t)((b * 2 + 1) * J + j) * HW);
    float4* o0 = reinterpret_cast<float4*>(out + IMG2_SZ + (size_t)((b * 2 + 0) * J + j) * HW);
    float4* o1 = reinterpret_cast<float4*>(out + IMG2_SZ + (size_t)((b * 2 + 1) * J + j) * HW);

    const float col0 = (float)((4 * tid) & 127);
    const int row0 = (4 * tid) >> 7;

    float s2 = 0.f, sx2 = 0.f, sy2 = 0.f;
#pragma unroll
    for (int k = 0; k < PER4; ++k) {
        float4 A = __ldcs(&hm0[tid + k * NT]);  // last consumer: evict-first
        float4 C = __ldcs(&hm1[tid + k * NT]);
        float rw = (float)(row0 + 8 * k);
        float4 f;
        f.x = w0 * A.x + w1 * C.x;
        f.y = w0 * A.y + w1 * C.y;
        f.z = w0 * A.z + w1 * C.z;
        f.w = w0 * A.w + w1 * C.w;
        __stcs(&o0[tid + k * NT], f);
        __stcs(&o1[tid + k * NT], f);
        float e0 = exp2f(f.x * SC);
        float e1 = exp2f(f.y * SC);
        float e2 = exp2f(f.z * SC);
        float e3 = exp2f(f.w * SC);
        float es = (e0 + e1) + (e2 + e3);
        s2 += es;
        sx2 += col0 * es + (e1 + 2.f * e2 + 3.f * e3);
        sy2 += rw * es;
    }

    // Batched 3-quantity reduction (2 barriers; 1 FULL warp stage 2)
    {
        float v[3] = {s2, sx2, sy2};
#pragma unroll
        for (int q = 0; q < 3; ++q) {
#pragma unroll
            for (int o = 16; o; o >>= 1)
                v[q] += __shfl_xor_sync(0xffffffffu, v[q], o);
        }
        if (lane == 0) {
#pragma unroll
            for (int q = 0; q < 3; ++q) sw[wid][q] = v[q];
        }
        __syncthreads();
        if (tid < 32) {  // 1 FULL warp: g = tid>>3 (0..3; group 3 zero-padded)
            int g = tid >> 3, e = tid & 7;
            float x = (g < 3) ? sw[e][g] : 0.f;
#pragma unroll
            for (int o = 4; o; o >>= 1)
                x += __shfl_xor_sync(0xffffffffu, x, o);
            if (e == 0 && g < 3) sres[g] = x;
        }
        __syncthreads();
    }

    if (tid == 0) {
        float x2 = 4.f * sres[1] / sres[0];
        float y2 = 4.f * sres[2] / sres[0];
        int base = b * (V * 2 * J);  // img2 layout (B, V, 2, J)
        out[base + 0 * J + j] = x2;
        out[base + 1 * J + j] = y2;
        out[base + 2 * J + j] = x2;
        out[base + 3 * J + j] = y2;
    }
}

}  // namespace

extern "C" void kernel_launch(void* const* d_in, const int* in_sizes, int n_in,
                              void* d_out, int out_size) {
    const float* hms  = (const float*)d_in[0];
    const float* APK  = (const float*)d_in[1];
    const float* APT  = (const float*)d_in[2];
    const float* LATK = (const float*)d_in[3];
    const float* LATT = (const float*)d_in[4];
    float* out = (float*)d_out;
    dim3 grid(J, B);
    adafuse_weights_kernel<<<grid, NT>>>(hms, APK, APT, LATK, LATT);
    adafuse_fuse_kernel<<<grid, NT>>>(hms, out);
}

// round 10
// speedup vs baseline: 2.2221x; 1.0009x over previous
#include <cuda_runtime.h>

namespace {

constexpr int B = 32, V = 2, J = 17, H = 128, W = 128;
constexpr int HW = H * W;                 // 16384
constexpr int NT = 256;                   // threads per block
constexpr int PER4 = HW / (4 * NT);       // 16 float4 per thread per view
constexpr int IMG2_SZ = B * V * 2 * J;    // 2176 floats (first output)
constexpr float SC = 28.85390081777927f;  // (1/0.05) * log2(e)

__device__ float g_w[B * J * 2];          // per-(b,j) fused coefficients

__device__ __forceinline__ void inv3x3(const float* m, float inv[3][3]) {
    float a = m[0], b = m[1], c = m[2];
    float d = m[3], e = m[4], f = m[5];
    float g = m[6], h = m[7], i = m[8];
    float A = (e * i - f * h);
    float Bm = -(d * i - f * g);
    float C = (d * h - e * g);
    float det = a * A + b * Bm + c * C;
    float id = 1.0f / det;
    inv[0][0] = A * id;               inv[0][1] = -(b * i - c * h) * id; inv[0][2] = (b * f - c * e) * id;
    inv[1][0] = Bm * id;              inv[1][1] = (a * i - c * g) * id;  inv[1][2] = -(a * f - c * d) * id;
    inv[2][0] = C * id;               inv[2][1] = -(a * h - b * g) * id; inv[2][2] = (a * e - b * d) * id;
}

__device__ __forceinline__ float epi_dist(const float F[3][3], const float xi[3], const float xj[3]) {
    float l0 = F[0][0] * xj[0] + F[0][1] * xj[1] + F[0][2] * xj[2];
    float l1 = F[1][0] * xj[0] + F[1][1] * xj[1] + F[1][2] * xj[2];
    float l2 = F[2][0] * xj[0] + F[2][1] * xj[1] + F[2][2] * xj[2];
    float s = xi[0] * l0 + xi[1] * l1 + xi[2] * l2;
    float lp0 = F[0][0] * xi[0] + F[1][0] * xi[1] + F[2][0] * xi[2];
    float lp1 = F[0][1] * xi[0] + F[1][1] * xi[1] + F[2][1] * xi[2];
    float div = l0 * l0 + l1 * l1 + lp0 * lp0 + lp1 * lp1;
    return sqrtf(s * s / (div + 1e-12f));
}

// ============================================================================
// Kernel 1: per-(b,j) view moments + geometry -> fused coefficients w0, w1.
// Pure streaming read of both heatmap views (leaves them resident in L2).
// ============================================================================
__global__ __launch_bounds__(NT) void adafuse_weights_kernel(
    const float* __restrict__ hms,
    const float* __restrict__ APK, const float* __restrict__ APT,
    const float* __restrict__ LATK, const float* __restrict__ LATT)
{
    __shared__ float sw[8][9];
    __shared__ float sres[10];
    __shared__ float sgeom[50];

    const int j = blockIdx.x;
    const int b = blockIdx.y;
    const int tid = threadIdx.x;
    const int wid = tid >> 5;
    const int lane = tid & 31;

    if (tid < 16)       sgeom[tid] = APT[b * 16 + tid];
    else if (tid < 32)  sgeom[tid] = LATT[b * 16 + (tid - 16)];
    else if (tid < 41)  sgeom[tid] = APK[b * 9 + (tid - 32)];
    else if (tid < 50)  sgeom[tid] = LATK[b * 9 + (tid - 41)];

    const float4* hm0 = reinterpret_cast<const float4*>(hms + (size_t)((b * 2 + 0) * J + j) * HW);
    const float4* hm1 = reinterpret_cast<const float4*>(hms + (size_t)((b * 2 + 1) * J + j) * HW);

    // element index (tid,k,comp) = 4*tid + 1024*k + comp
    const float col0 = (float)((4 * tid) & 127);
    const int row0 = (4 * tid) >> 7;

    // No max-subtraction: inputs in [0,1) -> exp2f(x*SC) <= 2^28.9, fp32-safe;
    // softmax is scale-invariant.
    float m0 = -1e30f, m1 = -1e30f;
    float s0 = 0.f, sx0 = 0.f, sy0 = 0.f;
    float s1 = 0.f, sx1 = 0.f, sy1 = 0.f;
#pragma unroll
    for (int k = 0; k < PER4; ++k) {
        float4 A = hm0[tid + k * NT];
        float4 C = hm1[tid + k * NT];
        float rw = (float)(row0 + 8 * k);
        m0 = fmaxf(m0, fmaxf(fmaxf(A.x, A.y), fmaxf(A.z, A.w)));
        m1 = fmaxf(m1, fmaxf(fmaxf(C.x, C.y), fmaxf(C.z, C.w)));
        float e0 = exp2f(A.x * SC);
        float e1 = exp2f(A.y * SC);
        float e2 = exp2f(A.z * SC);
        float e3 = exp2f(A.w * SC);
        float es = (e0 + e1) + (e2 + e3);
        s0 += es;
        sx0 += col0 * es + (e1 + 2.f * e2 + 3.f * e3);
        sy0 += rw * es;
        float f0 = exp2f(C.x * SC);
        float f1 = exp2f(C.y * SC);
        float f2 = exp2f(C.z * SC);
        float f3 = exp2f(C.w * SC);
        float fs = (f0 + f1) + (f2 + f3);
        s1 += fs;
        sx1 += col0 * fs + (f1 + 2.f * f2 + 3.f * f3);
        sy1 += rw * fs;
    }

    // Batched 8-quantity block reduction over 8 warps (2 barriers)
    {
        float v[8] = {m0, m1, s0, sx0, sy0, s1, sx1, sy1};
#pragma unroll
        for (int q = 0; q < 8; ++q) {
#pragma unroll
            for (int o = 16; o; o >>= 1) {
                float t = __shfl_xor_sync(0xffffffffu, v[q], o);
                v[q] = (q < 2) ? fmaxf(v[q], t) : (v[q] + t);
            }
        }
        if (lane == 0) {
#pragma unroll
            for (int q = 0; q < 8; ++q) sw[wid][q] = v[q];
        }
        __syncthreads();
        if (tid < 64) {  // 2 FULL warps: quantity g = tid>>3, partial e = tid&7
            int g = tid >> 3, e = tid & 7;
            float x = sw[e][g];
#pragma unroll
            for (int o = 4; o; o >>= 1) {
                float t = __shfl_xor_sync(0xffffffffu, x, o);
                x = (g < 2) ? fmaxf(x, t) : (x + t);
            }
            if (e == 0) sres[g] = x;
        }
        __syncthreads();
    }

    if (tid == 0) {
        const float* T0p = sgeom;
        const float* T1p = sgeom + 16;
        const float* K0 = sgeom + 32;
        const float* K1 = sgeom + 41;
        float R0[3][3], R1[3][3], t0v[3], t1v[3];
#pragma unroll
        for (int m = 0; m < 3; ++m) {
#pragma unroll
            for (int n = 0; n < 3; ++n) {
                R0[m][n] = T0p[m * 4 + n];
                R1[m][n] = T1p[m * 4 + n];
            }
            t0v[m] = T0p[m * 4 + 3];
            t1v[m] = T1p[m * 4 + 3];
        }
        float iK0[3][3], iK1[3][3];
        inv3x3(K0, iK0);
        inv3x3(K1, iK1);

        float r01[3][3];
#pragma unroll
        for (int m = 0; m < 3; ++m)
#pragma unroll
            for (int n = 0; n < 3; ++n)
                r01[m][n] = R0[m][0] * R1[n][0] + R0[m][1] * R1[n][1] + R0[m][2] * R1[n][2];

        float t01[3], t10[3];
#pragma unroll
        for (int m = 0; m < 3; ++m) {
            t01[m] = t0v[m] - (r01[m][0] * t1v[0] + r01[m][1] * t1v[1] + r01[m][2] * t1v[2]);
            t10[m] = t1v[m] - (r01[0][m] * t0v[0] + r01[1][m] * t0v[1] + r01[2][m] * t0v[2]);
        }

        float M01[3][3], M10[3][3];
#pragma unroll
        for (int n = 0; n < 3; ++n) {
            M01[0][n] = -t01[2] * r01[1][n] + t01[1] * r01[2][n];
            M01[1][n] =  t01[2] * r01[0][n] - t01[0] * r01[2][n];
            M01[2][n] = -t01[1] * r01[0][n] + t01[0] * r01[1][n];
            M10[0][n] = -t10[2] * r01[n][1] + t10[1] * r01[n][2];
            M10[1][n] =  t10[2] * r01[n][0] - t10[0] * r01[n][2];
            M10[2][n] = -t10[1] * r01[n][0] + t10[0] * r01[n][1];
        }

        float tmp[3][3], F01[3][3], F10[3][3];
#pragma unroll
        for (int p = 0; p < 3; ++p)
#pragma unroll
            for (int l = 0; l < 3; ++l)
                tmp[p][l] = M01[p][0] * iK1[0][l] + M01[p][1] * iK1[1][l] + M01[p][2] * iK1[2][l];
#pragma unroll
        for (int m = 0; m < 3; ++m)
#pragma unroll
            for (int l = 0; l < 3; ++l)
                F01[m][l] = iK0[0][m] * tmp[0][l] + iK0[1][m] * tmp[1][l] + iK0[2][m] * tmp[2][l];
#pragma unroll
        for (int p = 0; p < 3; ++p)
#pragma unroll
            for (int l = 0; l < 3; ++l)
                tmp[p][l] = M10[p][0] * iK0[0][l] + M10[p][1] * iK0[1][l] + M10[p][2] * iK0[2][l];
#pragma unroll
        for (int m = 0; m < 3; ++m)
#pragma unroll
            for (int l = 0; l < 3; ++l)
                F10[m][l] = iK1[0][m] * tmp[0][l] + iK1[1][m] * tmp[1][l] + iK1[2][m] * tmp[2][l];

        float rm0 = sres[0], rm1 = sres[1];
        float img0[3] = {4.f * sres[3] / sres[2], 4.f * sres[4] / sres[2], 1.f};
        float img1[3] = {4.f * sres[6] / sres[5], 4.f * sres[7] / sres[5], 1.f};
        float d01 = epi_dist(F01, img0, img1);
        float d10 = epi_dist(F10, img1, img0);

        float sc0 = rm0 - d01;
        float sc1 = rm1 - d10;
        float mm = fmaxf(sc0, sc1);
        float e0 = __expf(sc0 - mm), e1 = __expf(sc1 - mm);
        float inv = 1.f / (e0 + e1);
        float mv0 = (rm0 > 0.01f) ? rm0 : 1e6f;
        float mv1 = (rm1 > 0.01f) ? rm1 : 1e6f;
        g_w[(b * J + j) * 2 + 0] = e0 * inv / mv0;
        g_w[(b * J + j) * 2 + 1] = e1 * inv / mv1;
    }
}

// ============================================================================
// Kernel 2: fuse (reads hit L2 left warm by k1), streaming-store both output
// slices, fused soft-argmax -> img2.
// ============================================================================
__global__ __launch_bounds__(NT) void adafuse_fuse_kernel(
    const float* __restrict__ hms,
    float* __restrict__ out)
{
    __shared__ float sw[8][3];
    __shared__ float sres[3];

    const int j = blockIdx.x;
    const int b = blockIdx.y;
    const int tid = threadIdx.x;
    const int wid = tid >> 5;
    const int lane = tid & 31;

    const float w0 = g_w[(b * J + j) * 2 + 0];
    const float w1 = g_w[(b * J + j) * 2 + 1];

    const float4* hm0 = reinterpret_cast<const float4*>(hms + (size_t)((b * 2 + 0) * J + j) * HW);
    const float4* hm1 = reinterpret_cast<const float4*>(hms + (size_t)((b * 2 + 1) * J + j) * HW);
    float4* o0 = reinterpret_cast<float4*>(out + IMG2_SZ + (size_t)((b * 2 + 0) * J + j) * HW);
    float4* o1 = reinterpret_cast<float4*>(out + IMG2_SZ + (size_t)((b * 2 + 1) * J + j) * HW);

    const float col0 = (float)((4 * tid) & 127);
    const int row0 = (4 * tid) >> 7;

    float s2 = 0.f, sx2 = 0.f, sy2 = 0.f;
#pragma unroll
    for (int k = 0; k < PER4; ++k) {
        float4 A = __ldcs(&hm0[tid + k * NT]);  // last consumer: evict-first
        float4 C = __ldcs(&hm1[tid + k * NT]);
        float rw = (float)(row0 + 8 * k);
        float4 f;
        f.x = w0 * A.x + w1 * C.x;
        f.y = w0 * A.y + w1 * C.y;
        f.z = w0 * A.z + w1 * C.z;
        f.w = w0 * A.w + w1 * C.w;
        __stcs(&o0[tid + k * NT], f);
        __stcs(&o1[tid + k * NT], f);
        float e0 = exp2f(f.x * SC);
        float e1 = exp2f(f.y * SC);
        float e2 = exp2f(f.z * SC);
        float e3 = exp2f(f.w * SC);
        float es = (e0 + e1) + (e2 + e3);
        s2 += es;
        sx2 += col0 * es + (e1 + 2.f * e2 + 3.f * e3);
        sy2 += rw * es;
    }

    // Batched 3-quantity reduction (2 barriers; 1 FULL warp stage 2)
    {
        float v[3] = {s2, sx2, sy2};
#pragma unroll
        for (int q = 0; q < 3; ++q) {
#pragma unroll
            for (int o = 16; o; o >>= 1)
                v[q] += __shfl_xor_sync(0xffffffffu, v[q], o);
        }
        if (lane == 0) {
#pragma unroll
            for (int q = 0; q < 3; ++q) sw[wid][q] = v[q];
        }
        __syncthreads();
        if (tid < 32) {  // 1 FULL warp: g = tid>>3 (0..3; group 3 zero-padded)
            int g = tid >> 3, e = tid & 7;
            float x = (g < 3) ? sw[e][g] : 0.f;
#pragma unroll
            for (int o = 4; o; o >>= 1)
                x += __shfl_xor_sync(0xffffffffu, x, o);
            if (e == 0 && g < 3) sres[g] = x;
        }
        __syncthreads();
    }

    if (tid == 0) {
        float x2 = 4.f * sres[1] / sres[0];
        float y2 = 4.f * sres[2] / sres[0];
        int base = b * (V * 2 * J);  // img2 layout (B, V, 2, J)
        out[base + 0 * J + j] = x2;
        out[base + 1 * J + j] = y2;
        out[base + 2 * J + j] = x2;
        out[base + 3 * J + j] = y2;
    }
}

}  // namespace

extern "C" void kernel_launch(void* const* d_in, const int* in_sizes, int n_in,
                              void* d_out, int out_size) {
    const float* hms  = (const float*)d_in[0];
    const float* APK  = (const float*)d_in[1];
    const float* APT  = (const float*)d_in[2];
    const float* LATK = (const float*)d_in[3];
    const float* LATT = (const float*)d_in[4];
    float* out = (float*)d_out;
    dim3 grid(J, B);
    adafuse_weights_kernel<<<grid, NT>>>(hms, APK, APT, LATK, LATT);
    adafuse_fuse_kernel<<<grid, NT>>>(hms, out);
}

// round 11
// speedup vs baseline: 2.3387x; 1.0525x over previous
#include <cuda_runtime.h>

namespace {

constexpr int B = 32, V = 2, J = 17, H = 128, W = 128;
constexpr int HW = H * W;                 // 16384
constexpr int NT = 256;                   // threads per block
constexpr int PER4 = HW / (4 * NT);       // 16 float4 per thread per view
constexpr int IMG2_SZ = B * V * 2 * J;    // 2176 floats (first output)
constexpr float SC = 28.85390081777927f;  // (1/0.05) * log2(e)

__device__ float g_w[B * J * 2];          // per-(b,j) fused coefficients

__device__ __forceinline__ void inv3x3(const float* m, float inv[3][3]) {
    float a = m[0], b = m[1], c = m[2];
    float d = m[3], e = m[4], f = m[5];
    float g = m[6], h = m[7], i = m[8];
    float A = (e * i - f * h);
    float Bm = -(d * i - f * g);
    float C = (d * h - e * g);
    float det = a * A + b * Bm + c * C;
    float id = 1.0f / det;
    inv[0][0] = A * id;               inv[0][1] = -(b * i - c * h) * id; inv[0][2] = (b * f - c * e) * id;
    inv[1][0] = Bm * id;              inv[1][1] = (a * i - c * g) * id;  inv[1][2] = -(a * f - c * d) * id;
    inv[2][0] = C * id;               inv[2][1] = -(a * h - b * g) * id; inv[2][2] = (a * e - b * d) * id;
}

__device__ __forceinline__ float epi_dist(const float F[3][3], const float xi[3], const float xj[3]) {
    float l0 = F[0][0] * xj[0] + F[0][1] * xj[1] + F[0][2] * xj[2];
    float l1 = F[1][0] * xj[0] + F[1][1] * xj[1] + F[1][2] * xj[2];
    float l2 = F[2][0] * xj[0] + F[2][1] * xj[1] + F[2][2] * xj[2];
    float s = xi[0] * l0 + xi[1] * l1 + xi[2] * l2;
    float lp0 = F[0][0] * xi[0] + F[1][0] * xi[1] + F[2][0] * xi[2];
    float lp1 = F[0][1] * xi[0] + F[1][1] * xi[1] + F[2][1] * xi[2];
    float div = l0 * l0 + l1 * l1 + lp0 * lp0 + lp1 * lp1;
    return sqrtf(s * s / (div + 1e-12f));
}

// ============================================================================
// Kernel 1: per-(b,j) view moments + geometry -> fused coefficients w0, w1.
// Pure streaming read; leaves the heatmaps resident in L2 for kernel 2.
// ============================================================================
__global__ __launch_bounds__(NT, 6) void adafuse_weights_kernel(
    const float* __restrict__ hms,
    const float* __restrict__ APK, const float* __restrict__ APT,
    const float* __restrict__ LATK, const float* __restrict__ LATT)
{
    __shared__ float sw[8][9];
    __shared__ float sres[10];
    __shared__ float sgeom[50];

    const int j = blockIdx.x;
    const int b = blockIdx.y;
    const int tid = threadIdx.x;
    const int wid = tid >> 5;
    const int lane = tid & 31;

    if (tid < 16)       sgeom[tid] = APT[b * 16 + tid];
    else if (tid < 32)  sgeom[tid] = LATT[b * 16 + (tid - 16)];
    else if (tid < 41)  sgeom[tid] = APK[b * 9 + (tid - 32)];
    else if (tid < 50)  sgeom[tid] = LATK[b * 9 + (tid - 41)];

    const float4* hm0 = reinterpret_cast<const float4*>(hms + (size_t)((b * 2 + 0) * J + j) * HW);
    const float4* hm1 = reinterpret_cast<const float4*>(hms + (size_t)((b * 2 + 1) * J + j) * HW);

    // element index (tid,k,comp) = 4*tid + 1024*k + comp
    const float col0 = (float)((4 * tid) & 127);
    const int row0 = (4 * tid) >> 7;

    // No max-subtraction: inputs in [0,1) -> exp2f(x*SC) <= 2^28.9, fp32-safe;
    // softmax is scale-invariant.
    float m0 = -1e30f, m1 = -1e30f;
    float s0 = 0.f, sx0 = 0.f, sy0 = 0.f;
    float s1 = 0.f, sx1 = 0.f, sy1 = 0.f;
#pragma unroll
    for (int k = 0; k < PER4; ++k) {
        float4 A = hm0[tid + k * NT];
        float4 C = hm1[tid + k * NT];
        float rw = (float)(row0 + 8 * k);
        m0 = fmaxf(m0, fmaxf(fmaxf(A.x, A.y), fmaxf(A.z, A.w)));
        m1 = fmaxf(m1, fmaxf(fmaxf(C.x, C.y), fmaxf(C.z, C.w)));
        float e0 = exp2f(A.x * SC);
        float e1 = exp2f(A.y * SC);
        float e2 = exp2f(A.z * SC);
        float e3 = exp2f(A.w * SC);
        float es = (e0 + e1) + (e2 + e3);
        s0 += es;
        sx0 += col0 * es + (e1 + 2.f * e2 + 3.f * e3);
        sy0 += rw * es;
        float f0 = exp2f(C.x * SC);
        float f1 = exp2f(C.y * SC);
        float f2 = exp2f(C.z * SC);
        float f3 = exp2f(C.w * SC);
        float fs = (f0 + f1) + (f2 + f3);
        s1 += fs;
        sx1 += col0 * fs + (f1 + 2.f * f2 + 3.f * f3);
        sy1 += rw * fs;
    }

    // Batched 8-quantity block reduction over 8 warps (2 barriers)
    {
        float v[8] = {m0, m1, s0, sx0, sy0, s1, sx1, sy1};
#pragma unroll
        for (int q = 0; q < 8; ++q) {
#pragma unroll
            for (int o = 16; o; o >>= 1) {
                float t = __shfl_xor_sync(0xffffffffu, v[q], o);
                v[q] = (q < 2) ? fmaxf(v[q], t) : (v[q] + t);
            }
        }
        if (lane == 0) {
#pragma unroll
            for (int q = 0; q < 8; ++q) sw[wid][q] = v[q];
        }
        __syncthreads();
        if (tid < 64) {  // 2 FULL warps: quantity g = tid>>3, partial e = tid&7
            int g = tid >> 3, e = tid & 7;
            float x = sw[e][g];
#pragma unroll
            for (int o = 4; o; o >>= 1) {
                float t = __shfl_xor_sync(0xffffffffu, x, o);
                x = (g < 2) ? fmaxf(x, t) : (x + t);
            }
            if (e == 0) sres[g] = x;
        }
        __syncthreads();
    }

    if (tid == 0) {
        const float* T0p = sgeom;
        const float* T1p = sgeom + 16;
        const float* K0 = sgeom + 32;
        const float* K1 = sgeom + 41;
        float R0[3][3], R1[3][3], t0v[3], t1v[3];
#pragma unroll
        for (int m = 0; m < 3; ++m) {
#pragma unroll
            for (int n = 0; n < 3; ++n) {
                R0[m][n] = T0p[m * 4 + n];
                R1[m][n] = T1p[m * 4 + n];
            }
            t0v[m] = T0p[m * 4 + 3];
            t1v[m] = T1p[m * 4 + 3];
        }
        float iK0[3][3], iK1[3][3];
        inv3x3(K0, iK0);
        inv3x3(K1, iK1);

        float r01[3][3];
#pragma unroll
        for (int m = 0; m < 3; ++m)
#pragma unroll
            for (int n = 0; n < 3; ++n)
                r01[m][n] = R0[m][0] * R1[n][0] + R0[m][1] * R1[n][1] + R0[m][2] * R1[n][2];

        float t01[3], t10[3];
#pragma unroll
        for (int m = 0; m < 3; ++m) {
            t01[m] = t0v[m] - (r01[m][0] * t1v[0] + r01[m][1] * t1v[1] + r01[m][2] * t1v[2]);
            t10[m] = t1v[m] - (r01[0][m] * t0v[0] + r01[1][m] * t0v[1] + r01[2][m] * t0v[2]);
        }

        float M01[3][3], M10[3][3];
#pragma unroll
        for (int n = 0; n < 3; ++n) {
            M01[0][n] = -t01[2] * r01[1][n] + t01[1] * r01[2][n];
            M01[1][n] =  t01[2] * r01[0][n] - t01[0] * r01[2][n];
            M01[2][n] = -t01[1] * r01[0][n] + t01[0] * r01[1][n];
            M10[0][n] = -t10[2] * r01[n][1] + t10[1] * r01[n][2];
            M10[1][n] =  t10[2] * r01[n][0] - t10[0] * r01[n][2];
            M10[2][n] = -t10[1] * r01[n][0] + t10[0] * r01[n][1];
        }

        float tmp[3][3], F01[3][3], F10[3][3];
#pragma unroll
        for (int p = 0; p < 3; ++p)
#pragma unroll
            for (int l = 0; l < 3; ++l)
                tmp[p][l] = M01[p][0] * iK1[0][l] + M01[p][1] * iK1[1][l] + M01[p][2] * iK1[2][l];
#pragma unroll
        for (int m = 0; m < 3; ++m)
#pragma unroll
            for (int l = 0; l < 3; ++l)
                F01[m][l] = iK0[0][m] * tmp[0][l] + iK0[1][m] * tmp[1][l] + iK0[2][m] * tmp[2][l];
#pragma unroll
        for (int p = 0; p < 3; ++p)
#pragma unroll
            for (int l = 0; l < 3; ++l)
                tmp[p][l] = M10[p][0] * iK0[0][l] + M10[p][1] * iK0[1][l] + M10[p][2] * iK0[2][l];
#pragma unroll
        for (int m = 0; m < 3; ++m)
#pragma unroll
            for (int l = 0; l < 3; ++l)
                F10[m][l] = iK1[0][m] * tmp[0][l] + iK1[1][m] * tmp[1][l] + iK1[2][m] * tmp[2][l];

        float rm0 = sres[0], rm1 = sres[1];
        float img0[3] = {4.f * sres[3] / sres[2], 4.f * sres[4] / sres[2], 1.f};
        float img1[3] = {4.f * sres[6] / sres[5], 4.f * sres[7] / sres[5], 1.f};
        float d01 = epi_dist(F01, img0, img1);
        float d10 = epi_dist(F10, img1, img0);

        float sc0 = rm0 - d01;
        float sc1 = rm1 - d10;
        float mm = fmaxf(sc0, sc1);
        float e0 = __expf(sc0 - mm), e1 = __expf(sc1 - mm);
        float inv = 1.f / (e0 + e1);
        float mv0 = (rm0 > 0.01f) ? rm0 : 1e6f;
        float mv1 = (rm1 > 0.01f) ? rm1 : 1e6f;
        g_w[(b * J + j) * 2 + 0] = e0 * inv / mv0;
        g_w[(b * J + j) * 2 + 1] = e1 * inv / mv1;
    }
}

// ============================================================================
// Kernel 2: fuse (reads hit L2 left warm by k1 — default caching to keep
// them resident), streaming-store both output slices, fused soft-argmax.
// __launch_bounds__(256, 6): 48 warps/SM to hide L2-hit latency + store drain.
// ============================================================================
__global__ __launch_bounds__(NT, 6) void adafuse_fuse_kernel(
    const float* __restrict__ hms,
    float* __restrict__ out)
{
    __shared__ float sw[8][3];
    __shared__ float sres[3];

    const int j = blockIdx.x;
    const int b = blockIdx.y;
    const int tid = threadIdx.x;
    const int wid = tid >> 5;
    const int lane = tid & 31;

    const float w0 = g_w[(b * J + j) * 2 + 0];
    const float w1 = g_w[(b * J + j) * 2 + 1];

    const float4* hm0 = reinterpret_cast<const float4*>(hms + (size_t)((b * 2 + 0) * J + j) * HW);
    const float4* hm1 = reinterpret_cast<const float4*>(hms + (size_t)((b * 2 + 1) * J + j) * HW);
    float4* o0 = reinterpret_cast<float4*>(out + IMG2_SZ + (size_t)((b * 2 + 0) * J + j) * HW);
    float4* o1 = reinterpret_cast<float4*>(out + IMG2_SZ + (size_t)((b * 2 + 1) * J + j) * HW);

    const float col0 = (float)((4 * tid) & 127);
    const int row0 = (4 * tid) >> 7;

    float s2 = 0.f, sx2 = 0.f, sy2 = 0.f;
#pragma unroll
    for (int k = 0; k < PER4; ++k) {
        float4 A = hm0[tid + k * NT];  // L2 hit (parked by k1)
        float4 C = hm1[tid + k * NT];
        float rw = (float)(row0 + 8 * k);
        float4 f;
        f.x = w0 * A.x + w1 * C.x;
        f.y = w0 * A.y + w1 * C.y;
        f.z = w0 * A.z + w1 * C.z;
        f.w = w0 * A.w + w1 * C.w;
        __stcs(&o0[tid + k * NT], f);
        __stcs(&o1[tid + k * NT], f);
        float e0 = exp2f(f.x * SC);
        float e1 = exp2f(f.y * SC);
        float e2 = exp2f(f.z * SC);
        float e3 = exp2f(f.w * SC);
        float es = (e0 + e1) + (e2 + e3);
        s2 += es;
        sx2 += col0 * es + (e1 + 2.f * e2 + 3.f * e3);
        sy2 += rw * es;
    }

    // Batched 3-quantity reduction (2 barriers; 1 FULL warp stage 2)
    {
        float v[3] = {s2, sx2, sy2};
#pragma unroll
        for (int q = 0; q < 3; ++q) {
#pragma unroll
            for (int o = 16; o; o >>= 1)
                v[q] += __shfl_xor_sync(0xffffffffu, v[q], o);
        }
        if (lane == 0) {
#pragma unroll
            for (int q = 0; q < 3; ++q) sw[wid][q] = v[q];
        }
        __syncthreads();
        if (tid < 32) {  // 1 FULL warp: g = tid>>3 (0..3; group 3 zero-padded)
            int g = tid >> 3, e = tid & 7;
            float x = (g < 3) ? sw[e][g] : 0.f;
#pragma unroll
            for (int o = 4; o; o >>= 1)
                x += __shfl_xor_sync(0xffffffffu, x, o);
            if (e == 0 && g < 3) sres[g] = x;
        }
        __syncthreads();
    }

    if (tid == 0) {
        float x2 = 4.f * sres[1] / sres[0];
        float y2 = 4.f * sres[2] / sres[0];
        int base = b * (V * 2 * J);  // img2 layout (B, V, 2, J)
        out[base + 0 * J + j] = x2;
        out[base + 1 * J + j] = y2;
        out[base + 2 * J + j] = x2;
        out[base + 3 * J + j] = y2;
    }
}

}  // namespace

extern "C" void kernel_launch(void* const* d_in, const int* in_sizes, int n_in,
                              void* d_out, int out_size) {
    const float* hms  = (const float*)d_in[0];
    const float* APK  = (const float*)d_in[1];
    const float* APT  = (const float*)d_in[2];
    const float* LATK = (const float*)d_in[3];
    const float* LATT = (const float*)d_in[4];
    float* out = (float*)d_out;
    dim3 grid(J, B);
    adafuse_weights_kernel<<<grid, NT>>>(hms, APK, APT, LATK, LATT);
    adafuse_fuse_kernel<<<grid, NT>>>(hms, out);
}

// round 12
// speedup vs baseline: 2.4461x; 1.0459x over previous
#include <cuda_runtime.h>

namespace {

constexpr int B = 32, V = 2, J = 17, H = 128, W = 128;
constexpr int HW = H * W;                 // 16384
constexpr int NT = 256;                   // kernel-1 threads
constexpr int NT2 = 384;                  // kernel-2 threads (12 warps)
constexpr int PER4 = HW / (4 * NT);       // 16 float4 per thread per view (k1)
constexpr int NV4 = HW / 4;               // 4096 float4 per view
constexpr int K2_FULL = NV4 / NT2;        // 10 full iterations
constexpr int K2_TAIL = NV4 - K2_FULL * NT2;  // 256 tail threads
constexpr int IMG2_SZ = B * V * 2 * J;    // 2176 floats (first output)
constexpr float SC = 28.85390081777927f;  // (1/0.05) * log2(e)

__device__ float g_w[B * J * 2];          // per-(b,j) fused coefficients

__device__ __forceinline__ void inv3x3(const float* m, float inv[3][3]) {
    float a = m[0], b = m[1], c = m[2];
    float d = m[3], e = m[4], f = m[5];
    float g = m[6], h = m[7], i = m[8];
    float A = (e * i - f * h);
    float Bm = -(d * i - f * g);
    float C = (d * h - e * g);
    float det = a * A + b * Bm + c * C;
    float id = 1.0f / det;
    inv[0][0] = A * id;               inv[0][1] = -(b * i - c * h) * id; inv[0][2] = (b * f - c * e) * id;
    inv[1][0] = Bm * id;              inv[1][1] = (a * i - c * g) * id;  inv[1][2] = -(a * f - c * d) * id;
    inv[2][0] = C * id;               inv[2][1] = -(a * h - b * g) * id; inv[2][2] = (a * e - b * d) * id;
}

__device__ __forceinline__ float epi_dist(const float F[3][3], const float xi[3], const float xj[3]) {
    float l0 = F[0][0] * xj[0] + F[0][1] * xj[1] + F[0][2] * xj[2];
    float l1 = F[1][0] * xj[0] + F[1][1] * xj[1] + F[1][2] * xj[2];
    float l2 = F[2][0] * xj[0] + F[2][1] * xj[1] + F[2][2] * xj[2];
    float s = xi[0] * l0 + xi[1] * l1 + xi[2] * l2;
    float lp0 = F[0][0] * xi[0] + F[1][0] * xi[1] + F[2][0] * xi[2];
    float lp1 = F[0][1] * xi[0] + F[1][1] * xi[1] + F[2][1] * xi[2];
    float div = l0 * l0 + l1 * l1 + lp0 * lp0 + lp1 * lp1;
    return sqrtf(s * s / (div + 1e-12f));
}

// ============================================================================
// Kernel 1: per-(b,j) view moments + geometry -> fused coefficients w0, w1.
// Pure streaming read; leaves the heatmaps resident in L2 for kernel 2.
// ============================================================================
__global__ __launch_bounds__(NT) void adafuse_weights_kernel(
    const float* __restrict__ hms,
    const float* __restrict__ APK, const float* __restrict__ APT,
    const float* __restrict__ LATK, const float* __restrict__ LATT)
{
    __shared__ float sw[8][9];
    __shared__ float sres[10];
    __shared__ float sgeom[50];

    const int j = blockIdx.x;
    const int b = blockIdx.y;
    const int tid = threadIdx.x;
    const int wid = tid >> 5;
    const int lane = tid & 31;

    if (tid < 16)       sgeom[tid] = APT[b * 16 + tid];
    else if (tid < 32)  sgeom[tid] = LATT[b * 16 + (tid - 16)];
    else if (tid < 41)  sgeom[tid] = APK[b * 9 + (tid - 32)];
    else if (tid < 50)  sgeom[tid] = LATK[b * 9 + (tid - 41)];

    const float4* hm0 = reinterpret_cast<const float4*>(hms + (size_t)((b * 2 + 0) * J + j) * HW);
    const float4* hm1 = reinterpret_cast<const float4*>(hms + (size_t)((b * 2 + 1) * J + j) * HW);

    const float col0 = (float)((4 * tid) & 127);
    const int row0 = (4 * tid) >> 7;

    // No max-subtraction: inputs in [0,1) -> exp2f(x*SC) <= 2^28.9, fp32-safe.
    float m0 = -1e30f, m1 = -1e30f;
    float s0 = 0.f, sx0 = 0.f, sy0 = 0.f;
    float s1 = 0.f, sx1 = 0.f, sy1 = 0.f;
#pragma unroll
    for (int k = 0; k < PER4; ++k) {
        float4 A = hm0[tid + k * NT];
        float4 C = hm1[tid + k * NT];
        float rw = (float)(row0 + 8 * k);
        m0 = fmaxf(m0, fmaxf(fmaxf(A.x, A.y), fmaxf(A.z, A.w)));
        m1 = fmaxf(m1, fmaxf(fmaxf(C.x, C.y), fmaxf(C.z, C.w)));
        float e0 = exp2f(A.x * SC);
        float e1 = exp2f(A.y * SC);
        float e2 = exp2f(A.z * SC);
        float e3 = exp2f(A.w * SC);
        float es = (e0 + e1) + (e2 + e3);
        s0 += es;
        sx0 += col0 * es + (e1 + 2.f * e2 + 3.f * e3);
        sy0 += rw * es;
        float f0 = exp2f(C.x * SC);
        float f1 = exp2f(C.y * SC);
        float f2 = exp2f(C.z * SC);
        float f3 = exp2f(C.w * SC);
        float fs = (f0 + f1) + (f2 + f3);
        s1 += fs;
        sx1 += col0 * fs + (f1 + 2.f * f2 + 3.f * f3);
        sy1 += rw * fs;
    }

    // Batched 8-quantity block reduction over 8 warps (2 barriers)
    {
        float v[8] = {m0, m1, s0, sx0, sy0, s1, sx1, sy1};
#pragma unroll
        for (int q = 0; q < 8; ++q) {
#pragma unroll
            for (int o = 16; o; o >>= 1) {
                float t = __shfl_xor_sync(0xffffffffu, v[q], o);
                v[q] = (q < 2) ? fmaxf(v[q], t) : (v[q] + t);
            }
        }
        if (lane == 0) {
#pragma unroll
            for (int q = 0; q < 8; ++q) sw[wid][q] = v[q];
        }
        __syncthreads();
        if (tid < 64) {  // 2 FULL warps
            int g = tid >> 3, e = tid & 7;
            float x = sw[e][g];
#pragma unroll
            for (int o = 4; o; o >>= 1) {
                float t = __shfl_xor_sync(0xffffffffu, x, o);
                x = (g < 2) ? fmaxf(x, t) : (x + t);
            }
            if (e == 0) sres[g] = x;
        }
        __syncthreads();
    }

    if (tid == 0) {
        const float* T0p = sgeom;
        const float* T1p = sgeom + 16;
        const float* K0 = sgeom + 32;
        const float* K1 = sgeom + 41;
        float R0[3][3], R1[3][3], t0v[3], t1v[3];
#pragma unroll
        for (int m = 0; m < 3; ++m) {
#pragma unroll
            for (int n = 0; n < 3; ++n) {
                R0[m][n] = T0p[m * 4 + n];
                R1[m][n] = T1p[m * 4 + n];
            }
            t0v[m] = T0p[m * 4 + 3];
            t1v[m] = T1p[m * 4 + 3];
        }
        float iK0[3][3], iK1[3][3];
        inv3x3(K0, iK0);
        inv3x3(K1, iK1);

        float r01[3][3];
#pragma unroll
        for (int m = 0; m < 3; ++m)
#pragma unroll
            for (int n = 0; n < 3; ++n)
                r01[m][n] = R0[m][0] * R1[n][0] + R0[m][1] * R1[n][1] + R0[m][2] * R1[n][2];

        float t01[3], t10[3];
#pragma unroll
        for (int m = 0; m < 3; ++m) {
            t01[m] = t0v[m] - (r01[m][0] * t1v[0] + r01[m][1] * t1v[1] + r01[m][2] * t1v[2]);
            t10[m] = t1v[m] - (r01[0][m] * t0v[0] + r01[1][m] * t0v[1] + r01[2][m] * t0v[2]);
        }

        float M01[3][3], M10[3][3];
#pragma unroll
        for (int n = 0; n < 3; ++n) {
            M01[0][n] = -t01[2] * r01[1][n] + t01[1] * r01[2][n];
            M01[1][n] =  t01[2] * r01[0][n] - t01[0] * r01[2][n];
            M01[2][n] = -t01[1] * r01[0][n] + t01[0] * r01[1][n];
            M10[0][n] = -t10[2] * r01[n][1] + t10[1] * r01[n][2];
            M10[1][n] =  t10[2] * r01[n][0] - t10[0] * r01[n][2];
            M10[2][n] = -t10[1] * r01[n][0] + t10[0] * r01[n][1];
        }

        float tmp[3][3], F01[3][3], F10[3][3];
#pragma unroll
        for (int p = 0; p < 3; ++p)
#pragma unroll
            for (int l = 0; l < 3; ++l)
                tmp[p][l] = M01[p][0] * iK1[0][l] + M01[p][1] * iK1[1][l] + M01[p][2] * iK1[2][l];
#pragma unroll
        for (int m = 0; m < 3; ++m)
#pragma unroll
            for (int l = 0; l < 3; ++l)
                F01[m][l] = iK0[0][m] * tmp[0][l] + iK0[1][m] * tmp[1][l] + iK0[2][m] * tmp[2][l];
#pragma unroll
        for (int p = 0; p < 3; ++p)
#pragma unroll
            for (int l = 0; l < 3; ++l)
                tmp[p][l] = M10[p][0] * iK0[0][l] + M10[p][1] * iK0[1][l] + M10[p][2] * iK0[2][l];
#pragma unroll
        for (int m = 0; m < 3; ++m)
#pragma unroll
            for (int l = 0; l < 3; ++l)
                F10[m][l] = iK1[0][m] * tmp[0][l] + iK1[1][m] * tmp[1][l] + iK1[2][m] * tmp[2][l];

        float rm0 = sres[0], rm1 = sres[1];
        float img0[3] = {4.f * sres[3] / sres[2], 4.f * sres[4] / sres[2], 1.f};
        float img1[3] = {4.f * sres[6] / sres[5], 4.f * sres[7] / sres[5], 1.f};
        float d01 = epi_dist(F01, img0, img1);
        float d10 = epi_dist(F10, img1, img0);

        float sc0 = rm0 - d01;
        float sc1 = rm1 - d10;
        float mm = fmaxf(sc0, sc1);
        float e0 = __expf(sc0 - mm), e1 = __expf(sc1 - mm);
        float inv = 1.f / (e0 + e1);
        float mv0 = (rm0 > 0.01f) ? rm0 : 1e6f;
        float mv1 = (rm1 > 0.01f) ? rm1 : 1e6f;
        g_w[(b * J + j) * 2 + 0] = e0 * inv / mv0;
        g_w[(b * J + j) * 2 + 1] = e1 * inv / mv1;
    }
}

// ============================================================================
// Kernel 2: fuse (reads mostly hit L2 parked by k1), streaming-store both
// output slices, fused soft-argmax. 384 threads = 12 warps/CTA so the
// grid carries 6528 warps (~69% occupancy) while all 544 CTAs stay
// co-resident (launch_bounds(384,4): 4 CTAs/SM within the 64K-reg file).
// NOTE: 384*4 floats = 1536 = 12*128 elements -> per-thread column is
// invariant across iterations; row advances by 12.
// ============================================================================
__global__ __launch_bounds__(NT2, 4) void adafuse_fuse_kernel(
    const float* __restrict__ hms,
    float* __restrict__ out)
{
    __shared__ float sw[12][3];
    __shared__ float sres[3];

    const int j = blockIdx.x;
    const int b = blockIdx.y;
    const int tid = threadIdx.x;
    const int wid = tid >> 5;
    const int lane = tid & 31;

    const float w0 = g_w[(b * J + j) * 2 + 0];
    const float w1 = g_w[(b * J + j) * 2 + 1];

    const float4* hm0 = reinterpret_cast<const float4*>(hms + (size_t)((b * 2 + 0) * J + j) * HW);
    const float4* hm1 = reinterpret_cast<const float4*>(hms + (size_t)((b * 2 + 1) * J + j) * HW);
    float4* o0 = reinterpret_cast<float4*>(out + IMG2_SZ + (size_t)((b * 2 + 0) * J + j) * HW);
    float4* o1 = reinterpret_cast<float4*>(out + IMG2_SZ + (size_t)((b * 2 + 1) * J + j) * HW);

    const float col0 = (float)((4 * tid) & 127);
    const int row0 = (4 * tid) >> 7;  // 0..11

    float s2 = 0.f, sx2 = 0.f, sy2 = 0.f;
#pragma unroll
    for (int k = 0; k < K2_FULL; ++k) {
        int idx = tid + k * NT2;
        float4 A = hm0[idx];
        float4 C = hm1[idx];
        float rw = (float)(row0 + 12 * k);
        float4 f;
        f.x = w0 * A.x + w1 * C.x;
        f.y = w0 * A.y + w1 * C.y;
        f.z = w0 * A.z + w1 * C.z;
        f.w = w0 * A.w + w1 * C.w;
        __stcs(&o0[idx], f);
        __stcs(&o1[idx], f);
        float e0 = exp2f(f.x * SC);
        float e1 = exp2f(f.y * SC);
        float e2 = exp2f(f.z * SC);
        float e3 = exp2f(f.w * SC);
        float es = (e0 + e1) + (e2 + e3);
        s2 += es;
        sx2 += col0 * es + (e1 + 2.f * e2 + 3.f * e3);
        sy2 += rw * es;
    }
    if (tid < K2_TAIL) {  // remaining 256 float4
        int idx = tid + K2_FULL * NT2;
        float4 A = hm0[idx];
        float4 C = hm1[idx];
        float rw = (float)(row0 + 12 * K2_FULL);
        float4 f;
        f.x = w0 * A.x + w1 * C.x;
        f.y = w0 * A.y + w1 * C.y;
        f.z = w0 * A.z + w1 * C.z;
        f.w = w0 * A.w + w1 * C.w;
        __stcs(&o0[idx], f);
        __stcs(&o1[idx], f);
        float e0 = exp2f(f.x * SC);
        float e1 = exp2f(f.y * SC);
        float e2 = exp2f(f.z * SC);
        float e3 = exp2f(f.w * SC);
        float es = (e0 + e1) + (e2 + e3);
        s2 += es;
        sx2 += col0 * es + (e1 + 2.f * e2 + 3.f * e3);
        sy2 += rw * es;
    }

    // Batched 3-quantity reduction over 12 warps (2 barriers).
    // Stage 2: 2 FULL warps, 16-lane groups (partials 12..15 zero-padded).
    {
        float v[3] = {s2, sx2, sy2};
#pragma unroll
        for (int q = 0; q < 3; ++q) {
#pragma unroll
            for (int o = 16; o; o >>= 1)
                v[q] += __shfl_xor_sync(0xffffffffu, v[q], o);
        }
        if (lane == 0) {
#pragma unroll
            for (int q = 0; q < 3; ++q) sw[wid][q] = v[q];
        }
        __syncthreads();
        if (tid < 64) {  // 2 FULL warps: group g = tid>>4 (0..3), partial e = tid&15
            int g = tid >> 4, e = tid & 15;
            float x = (g < 3 && e < 12) ? sw[e][g] : 0.f;
#pragma unroll
            for (int o = 8; o; o >>= 1)
                x += __shfl_xor_sync(0xffffffffu, x, o);
            if (e == 0 && g < 3) sres[g] = x;
        }
        __syncthreads();
    }

    if (tid == 0) {
        float x2 = 4.f * sres[1] / sres[0];
        float y2 = 4.f * sres[2] / sres[0];
        int base = b * (V * 2 * J);  // img2 layout (B, V, 2, J)
        out[base + 0 * J + j] = x2;
        out[base + 1 * J + j] = y2;
        out[base + 2 * J + j] = x2;
        out[base + 3 * J + j] = y2;
    }
}

}  // namespace

extern "C" void kernel_launch(void* const* d_in, const int* in_sizes, int n_in,
                              void* d_out, int out_size) {
    const float* hms  = (const float*)d_in[0];
    const float* APK  = (const float*)d_in[1];
    const float* APT  = (const float*)d_in[2];
    const float* LATK = (const float*)d_in[3];
    const float* LATT = (const float*)d_in[4];
    float* out = (float*)d_out;
    dim3 grid(J, B);
    adafuse_weights_kernel<<<grid, NT>>>(hms, APK, APT, LATK, LATT);
    adafuse_fuse_kernel<<<grid, NT2>>>(hms, out);
}